// round 1
// baseline (speedup 1.0000x reference)
#include <cuda_runtime.h>
#include <cuda_bf16.h>
#include <math.h>

// Problem constants
#define BB   32
#define SS   512
#define CC   16
#define DIN  256
#define DOUT 64

// Scratch (allocation-free rule: __device__ globals)
__device__ float g_uhat[(size_t)BB * CC * SS * DOUT]; // 64 MiB, layout [b][c][s][o]
__device__ float g_b[(size_t)BB * SS * CC];           // b_ij, layout [b][s][c]
__device__ float g_c[(size_t)BB * SS * CC];           // c_ij, layout [b][s][c]
__device__ float g_v[(size_t)BB * CC * DOUT];         // v_j,  layout [b][c][o]

// ---------------------------------------------------------------------------
// Kernel 1: u_hat[b,c,s,o] = sum_i x[b,s,i] * W[c,s,i,o]
// grid (S, C), 256 threads. X tile + W slab in dynamic smem.
// ---------------------------------------------------------------------------
#define XS_STRIDE 257  // pad to avoid bank conflicts on Xs[m][k]

__global__ void gemm_uhat_kernel(const float* __restrict__ x,
                                 const float* __restrict__ W) {
    extern __shared__ float smem[];
    float* Xs = smem;                       // [32][XS_STRIDE]
    float* Ws = smem + 32 * XS_STRIDE;      // [256][64]

    const int s = blockIdx.x;
    const int c = blockIdx.y;
    const int tid = threadIdx.x;

    // Load X tile: x[b, s, :] for all b
    for (int idx = tid; idx < 32 * 256; idx += 256) {
        int b = idx >> 8;
        int i = idx & 255;
        Xs[b * XS_STRIDE + i] = x[(size_t)b * SS * DIN + (size_t)s * DIN + i];
    }
    // Load W slab: W[c, s, :, :] (contiguous 256*64 floats)
    const float* Wp = W + ((size_t)c * SS + s) * (size_t)(DIN * DOUT);
    for (int idx = tid; idx < 256 * 64; idx += 256) {
        Ws[idx] = Wp[idx];
    }
    __syncthreads();

    const int tx = tid & 15;        // n group
    const int ty = tid >> 4;        // m pair
    const int m0 = ty;
    const int m1 = ty + 16;
    const int n  = tx * 4;

    float acc00 = 0.f, acc01 = 0.f, acc02 = 0.f, acc03 = 0.f;
    float acc10 = 0.f, acc11 = 0.f, acc12 = 0.f, acc13 = 0.f;

    const float* x0 = Xs + m0 * XS_STRIDE;
    const float* x1 = Xs + m1 * XS_STRIDE;

#pragma unroll 8
    for (int k = 0; k < 256; k++) {
        float a0 = x0[k];
        float a1 = x1[k];
        float4 bv = *(const float4*)&Ws[k * 64 + n];
        acc00 += a0 * bv.x; acc01 += a0 * bv.y; acc02 += a0 * bv.z; acc03 += a0 * bv.w;
        acc10 += a1 * bv.x; acc11 += a1 * bv.y; acc12 += a1 * bv.z; acc13 += a1 * bv.w;
    }

    float* o0 = g_uhat + (((size_t)m0 * CC + c) * SS + s) * DOUT + n;
    float* o1 = g_uhat + (((size_t)m1 * CC + c) * SS + s) * DOUT + n;
    *(float4*)o0 = make_float4(acc00, acc01, acc02, acc03);
    *(float4*)o1 = make_float4(acc10, acc11, acc12, acc13);
}

// ---------------------------------------------------------------------------
// Kernel 2: s_j = sum_s c_ij * u_hat  (per (b,c)), then squash -> v
// grid = B*C blocks, 256 threads. uniform=1 => c_ij = 1/16.
// ---------------------------------------------------------------------------
__global__ void sj_squash_kernel(float* __restrict__ d_out, int uniform, int write_out) {
    const int bc = blockIdx.x;          // b*C + c
    const int b  = bc >> 4;
    const int c  = bc & 15;
    const int tid = threadIdx.x;
    const int o  = tid & 63;
    const int sg = tid >> 6;            // 4 s-groups

    const float* up = g_uhat + (size_t)bc * SS * DOUT;

    float acc = 0.f;
    if (uniform) {
        for (int s = sg; s < SS; s += 4)
            acc += up[s * DOUT + o];
        acc *= (1.0f / 16.0f);
    } else {
        const float* cp = g_c + (size_t)b * SS * CC + c;  // c_ij[b][s][c]
        for (int s = sg; s < SS; s += 4)
            acc += cp[s * CC] * up[s * DOUT + o];
    }

    __shared__ float red[256];
    __shared__ float sj[64];
    __shared__ float scale;

    red[tid] = acc;
    __syncthreads();
    if (sg == 0) {
        sj[o] = red[o] + red[64 + o] + red[128 + o] + red[192 + o];
    }
    __syncthreads();
    if (tid == 0) {
        float t = 0.f;
        for (int i = 0; i < 64; i++) t += sj[i] * sj[i];
        float nrm = sqrtf(t);
        scale = nrm / (1.0f + nrm * nrm);
    }
    __syncthreads();
    if (sg == 0) {
        float val = sj[o] * scale;
        g_v[(size_t)bc * DOUT + o] = val;
        if (write_out) d_out[(size_t)bc * DOUT + o] = val;
    }
}

// ---------------------------------------------------------------------------
// Kernel 3: agreement  b_ij[b,s,c] (+)= sum_o u_hat[b,c,s,o] * v[b,c,o]
// grid = B*C blocks, 256 threads (8 warps, warp per s, strided)
// ---------------------------------------------------------------------------
__global__ void agreement_kernel(int accumulate) {
    const int bc = blockIdx.x;
    const int b  = bc >> 4;
    const int c  = bc & 15;
    const int warp = threadIdx.x >> 5;
    const int lane = threadIdx.x & 31;

    __shared__ float vs[64];
    if (threadIdx.x < 64) vs[threadIdx.x] = g_v[(size_t)bc * DOUT + threadIdx.x];
    __syncthreads();

    const float* up = g_uhat + (size_t)bc * SS * DOUT;
    float* bp = g_b + (size_t)b * SS * CC + c;

    for (int s = warp; s < SS; s += 8) {
        const float* u = up + s * DOUT;
        float d = u[lane] * vs[lane] + u[lane + 32] * vs[lane + 32];
#pragma unroll
        for (int off = 16; off; off >>= 1)
            d += __shfl_xor_sync(0xffffffffu, d, off);
        if (lane == 0) {
            if (accumulate) bp[s * CC] += d;
            else            bp[s * CC]  = d;
        }
    }
}

// ---------------------------------------------------------------------------
// Kernel 4: softmax over c:  c_ij[b,s,:] = softmax(b_ij[b,s,:])
// thread per (b,s); [b][s][c] layout so the 16 values are contiguous.
// ---------------------------------------------------------------------------
__global__ void softmax_kernel() {
    const int idx = blockIdx.x * blockDim.x + threadIdx.x;   // over B*S
    if (idx >= BB * SS) return;
    const float* bp = g_b + (size_t)idx * CC;
    float* cp = g_c + (size_t)idx * CC;

    float m = bp[0];
#pragma unroll
    for (int c = 1; c < CC; c++) m = fmaxf(m, bp[c]);
    float sum = 0.f;
    float e[CC];
#pragma unroll
    for (int c = 0; c < CC; c++) { e[c] = __expf(bp[c] - m); sum += e[c]; }
    float inv = 1.0f / sum;
#pragma unroll
    for (int c = 0; c < CC; c++) cp[c] = e[c] * inv;
}

// ---------------------------------------------------------------------------
extern "C" void kernel_launch(void* const* d_in, const int* in_sizes, int n_in,
                              void* d_out, int out_size) {
    const float* x = (const float*)d_in[0];   // [B,S,din]
    const float* W = (const float*)d_in[1];   // [C,S,din,dout]
    float* out = (float*)d_out;               // [B,C,dout]

    const int smem_bytes = (32 * XS_STRIDE + 256 * 64) * sizeof(float); // 98432
    cudaFuncSetAttribute(gemm_uhat_kernel,
                         cudaFuncAttributeMaxDynamicSharedMemorySize, smem_bytes);

    dim3 ggrid(SS, CC);
    gemm_uhat_kernel<<<ggrid, 256, smem_bytes>>>(x, W);

    // Routing iteration 0 (softmax of zeros -> uniform 1/16)
    sj_squash_kernel<<<BB * CC, 256>>>(out, /*uniform=*/1, /*write_out=*/0);
    agreement_kernel<<<BB * CC, 256>>>(/*accumulate=*/0);

    // Iteration 1
    softmax_kernel<<<(BB * SS + 255) / 256, 256>>>();
    sj_squash_kernel<<<BB * CC, 256>>>(out, 0, 0);
    agreement_kernel<<<BB * CC, 256>>>(/*accumulate=*/1);

    // Iteration 2 (final: write v_j to d_out)
    softmax_kernel<<<(BB * SS + 255) / 256, 256>>>();
    sj_squash_kernel<<<BB * CC, 256>>>(out, 0, /*write_out=*/1);
}

// round 2
// speedup vs baseline: 1.4651x; 1.4651x over previous
#include <cuda_runtime.h>
#include <cuda_bf16.h>
#include <math.h>
#include <stdint.h>

#define BB   32
#define SS   512
#define CC   16
#define DIN  256
#define DOUT 64

#define XPAD 264   // bf16 row stride for Xs[b][k]  (conflict-free fragment loads)
#define OPAD 72    // bf16 row stride for Ws[k][o]

// Scratch (allocation-free rule: __device__ globals)
__device__ float g_uhat[(size_t)BB * CC * SS * DOUT]; // 64 MiB, [b][c][s][o]
__device__ float g_b[(size_t)BB * SS * CC];           // b_ij [b][s][c]
__device__ float g_c[(size_t)BB * SS * CC];           // c_ij [b][s][c]

__device__ __forceinline__ uint32_t pack_bf2(float a, float b) {
    __nv_bfloat162 t = __floats2bfloat162_rn(a, b);
    return *reinterpret_cast<uint32_t*>(&t);
}

#define MMA_BF16(d, a, b)                                                     \
    asm volatile(                                                             \
        "mma.sync.aligned.m16n8k16.row.col.f32.bf16.bf16.f32 "                \
        "{%0,%1,%2,%3},{%4,%5,%6,%7},{%8,%9},{%0,%1,%2,%3};"                  \
        : "+f"(d[0]), "+f"(d[1]), "+f"(d[2]), "+f"(d[3])                      \
        : "r"(a[0]), "r"(a[1]), "r"(a[2]), "r"(a[3]), "r"(b[0]), "r"(b[1]))

// ---------------------------------------------------------------------------
// GEMM: u_hat[b,c,s,o] = sum_i x[b,s,i] * W[c,s,i,o]
// grid (S, C), 128 threads. Split-bf16 (hi/lo) 3-term tensor-core GEMM.
// M=32 (b), N=64 (o), K=256 (i).
// ---------------------------------------------------------------------------
__global__ void __launch_bounds__(128) gemm_uhat_kernel(const float* __restrict__ x,
                                                        const float* __restrict__ W) {
    extern __shared__ char raw[];
    __nv_bfloat16* Xh = (__nv_bfloat16*)raw;          // [32][XPAD]
    __nv_bfloat16* Xl = Xh + 32 * XPAD;
    __nv_bfloat16* Wh = Xl + 32 * XPAD;               // [256][OPAD]
    __nv_bfloat16* Wl = Wh + 256 * OPAD;

    const int s   = blockIdx.x;
    const int c   = blockIdx.y;
    const int tid = threadIdx.x;

    // ---- stage X tile (32 x 256 fp32) as hi/lo bf16 ----
    for (int i = tid; i < 2048; i += 128) {
        const int b = i >> 6;
        const int k = (i & 63) * 4;
        float4 f = ((const float4*)(x + ((size_t)b * SS + s) * DIN))[i & 63];
        float hx = __bfloat162float(__float2bfloat16(f.x));
        float hy = __bfloat162float(__float2bfloat16(f.y));
        float hz = __bfloat162float(__float2bfloat16(f.z));
        float hw = __bfloat162float(__float2bfloat16(f.w));
        *(uint32_t*)(Xh + b * XPAD + k)     = pack_bf2(f.x, f.y);
        *(uint32_t*)(Xh + b * XPAD + k + 2) = pack_bf2(f.z, f.w);
        *(uint32_t*)(Xl + b * XPAD + k)     = pack_bf2(f.x - hx, f.y - hy);
        *(uint32_t*)(Xl + b * XPAD + k + 2) = pack_bf2(f.z - hz, f.w - hw);
    }

    // ---- stage W slab (256 x 64 fp32) as hi/lo bf16 ----
    const float4* Wp4 = (const float4*)(W + ((size_t)c * SS + s) * (size_t)(DIN * DOUT));
    for (int i = tid; i < 4096; i += 128) {
        const int k = i >> 4;
        const int o = (i & 15) * 4;
        float4 f = Wp4[i];
        float hx = __bfloat162float(__float2bfloat16(f.x));
        float hy = __bfloat162float(__float2bfloat16(f.y));
        float hz = __bfloat162float(__float2bfloat16(f.z));
        float hw = __bfloat162float(__float2bfloat16(f.w));
        *(uint32_t*)(Wh + k * OPAD + o)     = pack_bf2(f.x, f.y);
        *(uint32_t*)(Wh + k * OPAD + o + 2) = pack_bf2(f.z, f.w);
        *(uint32_t*)(Wl + k * OPAD + o)     = pack_bf2(f.x - hx, f.y - hy);
        *(uint32_t*)(Wl + k * OPAD + o + 2) = pack_bf2(f.z - hz, f.w - hw);
    }
    __syncthreads();

    const int lane = tid & 31;
    const int warp = tid >> 5;
    const int nb   = warp * 16;          // this warp's N range [nb, nb+16)
    const int ar   = lane >> 2;          // 0..7
    const int kq   = (lane & 3) * 2;     // 0,2,4,6

    float acc[2][2][4];
#pragma unroll
    for (int mt = 0; mt < 2; mt++)
#pragma unroll
        for (int nt = 0; nt < 2; nt++)
#pragma unroll
            for (int r = 0; r < 4; r++) acc[mt][nt][r] = 0.f;

    const unsigned short* WhU = (const unsigned short*)Wh;
    const unsigned short* WlU = (const unsigned short*)Wl;

#pragma unroll 4
    for (int ks = 0; ks < 16; ks++) {
        const int k0 = ks * 16;

        uint32_t ah[2][4], al[2][4];
#pragma unroll
        for (int mt = 0; mt < 2; mt++) {
            const __nv_bfloat16* p = Xh + (ar + mt * 16) * XPAD + k0 + kq;
            const __nv_bfloat16* q = Xl + (ar + mt * 16) * XPAD + k0 + kq;
            ah[mt][0] = *(const uint32_t*)p;
            ah[mt][1] = *(const uint32_t*)(p + 8 * XPAD);
            ah[mt][2] = *(const uint32_t*)(p + 8);
            ah[mt][3] = *(const uint32_t*)(p + 8 * XPAD + 8);
            al[mt][0] = *(const uint32_t*)q;
            al[mt][1] = *(const uint32_t*)(q + 8 * XPAD);
            al[mt][2] = *(const uint32_t*)(q + 8);
            al[mt][3] = *(const uint32_t*)(q + 8 * XPAD + 8);
        }

        uint32_t bh[2][2], bl[2][2];
#pragma unroll
        for (int nt = 0; nt < 2; nt++) {
            const int n = nb + nt * 8 + ar;
            const int base = (k0 + kq) * OPAD + n;
            bh[nt][0] = (uint32_t)WhU[base]            | ((uint32_t)WhU[base + OPAD]     << 16);
            bh[nt][1] = (uint32_t)WhU[base + 8 * OPAD] | ((uint32_t)WhU[base + 9 * OPAD] << 16);
            bl[nt][0] = (uint32_t)WlU[base]            | ((uint32_t)WlU[base + OPAD]     << 16);
            bl[nt][1] = (uint32_t)WlU[base + 8 * OPAD] | ((uint32_t)WlU[base + 9 * OPAD] << 16);
        }

#pragma unroll
        for (int mt = 0; mt < 2; mt++)
#pragma unroll
            for (int nt = 0; nt < 2; nt++) {
                MMA_BF16(acc[mt][nt], ah[mt], bh[nt]);
                MMA_BF16(acc[mt][nt], ah[mt], bl[nt]);
                MMA_BF16(acc[mt][nt], al[mt], bh[nt]);
            }
    }

    // ---- store: u_hat[b][c][s][o] ----
#pragma unroll
    for (int mt = 0; mt < 2; mt++) {
        const int row = ar + mt * 16;
#pragma unroll
        for (int nt = 0; nt < 2; nt++) {
            const int o = nb + nt * 8 + kq;
            float* p0 = g_uhat + (((size_t)row * CC + c) * SS + s) * DOUT + o;
            float* p1 = g_uhat + (((size_t)(row + 8) * CC + c) * SS + s) * DOUT + o;
            *(float2*)p0 = make_float2(acc[mt][nt][0], acc[mt][nt][1]);
            *(float2*)p1 = make_float2(acc[mt][nt][2], acc[mt][nt][3]);
        }
    }
}

// ---------------------------------------------------------------------------
// Fused routing step for one (b,c): stage u_hat tile (512x64) in smem once,
// compute s_j (+squash -> v), then agreement dots -> b_ij.
// mode 0: uniform weights, b_ij  = dots
// mode 1: weighted,        b_ij += dots
// mode 2: weighted, final: write v to d_out, no dots
// ---------------------------------------------------------------------------
__global__ void __launch_bounds__(256) route_kernel(float* __restrict__ d_out, int mode) {
    extern __shared__ char raw[];
    float* us  = (float*)raw;        // [512*64]
    float* cs  = us + 32768;         // [512]
    float* red = cs + 512;           // [256]
    float* sj  = red + 256;          // [64]
    float* scl = sj + 64;            // [1]

    const int bc  = blockIdx.x;
    const int b   = bc >> 4;
    const int c   = bc & 15;
    const int tid = threadIdx.x;

    const float4* up4 = (const float4*)(g_uhat + (size_t)bc * SS * DOUT);
    float4* us4 = (float4*)us;
    for (int i = tid; i < 8192; i += 256) us4[i] = up4[i];
    if (mode != 0)
        for (int s = tid; s < SS; s += 256) cs[s] = g_c[((size_t)b * SS + s) * CC + c];
    __syncthreads();

    // s_j partial sums
    const int o  = tid & 63;
    const int sg = tid >> 6;
    float acc = 0.f;
    if (mode == 0) {
        for (int s = sg; s < SS; s += 4) acc += us[s * DOUT + o];
        acc *= (1.0f / 16.0f);
    } else {
        for (int s = sg; s < SS; s += 4) acc += cs[s] * us[s * DOUT + o];
    }
    red[tid] = acc;
    __syncthreads();
    if (tid < 64) sj[tid] = red[tid] + red[tid + 64] + red[tid + 128] + red[tid + 192];
    __syncthreads();

    // squash scale = n / (1 + n^2)
    if (tid < 32) {
        float t = sj[tid] * sj[tid] + sj[tid + 32] * sj[tid + 32];
#pragma unroll
        for (int off = 16; off; off >>= 1) t += __shfl_xor_sync(0xffffffffu, t, off);
        if (tid == 0) {
            float n = sqrtf(t);
            *scl = n / (1.0f + t);
        }
    }
    __syncthreads();
    const float sc = *scl;
    if (tid < 64) {
        float v = sj[tid] * sc;
        sj[tid] = v;
        if (mode == 2) d_out[(size_t)bc * DOUT + tid] = v;
    }
    __syncthreads();

    if (mode != 2) {
        const int warp = tid >> 5, lane = tid & 31;
        const float v0 = sj[lane];
        const float v1 = sj[lane + 32];
        float* bp = g_b + (size_t)b * SS * CC + c;
        for (int s = warp; s < SS; s += 8) {
            float d = us[s * DOUT + lane] * v0 + us[s * DOUT + lane + 32] * v1;
#pragma unroll
            for (int off = 16; off; off >>= 1) d += __shfl_xor_sync(0xffffffffu, d, off);
            if (lane == 0) {
                if (mode == 1) bp[s * CC] += d;
                else           bp[s * CC]  = d;
            }
        }
    }
}

// ---------------------------------------------------------------------------
// softmax over c: c_ij[b,s,:] = softmax(b_ij[b,s,:])
// ---------------------------------------------------------------------------
__global__ void softmax_kernel() {
    const int idx = blockIdx.x * blockDim.x + threadIdx.x;   // over B*S
    if (idx >= BB * SS) return;
    const float* bp = g_b + (size_t)idx * CC;
    float* cp = g_c + (size_t)idx * CC;

    float m = bp[0];
#pragma unroll
    for (int c = 1; c < CC; c++) m = fmaxf(m, bp[c]);
    float sum = 0.f;
    float e[CC];
#pragma unroll
    for (int c = 0; c < CC; c++) { e[c] = __expf(bp[c] - m); sum += e[c]; }
    float inv = 1.0f / sum;
#pragma unroll
    for (int c = 0; c < CC; c++) cp[c] = e[c] * inv;
}

// ---------------------------------------------------------------------------
extern "C" void kernel_launch(void* const* d_in, const int* in_sizes, int n_in,
                              void* d_out, int out_size) {
    const float* x = (const float*)d_in[0];   // [B,S,din]
    const float* W = (const float*)d_in[1];   // [C,S,din,dout]
    float* out = (float*)d_out;               // [B,C,dout]

    const int gsm = (2 * 32 * XPAD + 2 * 256 * OPAD) * (int)sizeof(__nv_bfloat16); // 107520
    cudaFuncSetAttribute(gemm_uhat_kernel,
                         cudaFuncAttributeMaxDynamicSharedMemorySize, gsm);
    const int rsm = (32768 + 512 + 256 + 64 + 8) * (int)sizeof(float);             // 134432
    cudaFuncSetAttribute(route_kernel,
                         cudaFuncAttributeMaxDynamicSharedMemorySize, rsm);

    dim3 ggrid(SS, CC);
    gemm_uhat_kernel<<<ggrid, 128, gsm>>>(x, W);

    route_kernel<<<BB * CC, 256, rsm>>>(out, 0);
    softmax_kernel<<<(BB * SS + 255) / 256, 256>>>();
    route_kernel<<<BB * CC, 256, rsm>>>(out, 1);
    softmax_kernel<<<(BB * SS + 255) / 256, 256>>>();
    route_kernel<<<BB * CC, 256, rsm>>>(out, 2);
}

// round 3
// speedup vs baseline: 2.1846x; 1.4911x over previous
#include <cuda_runtime.h>
#include <cuda_bf16.h>
#include <math.h>
#include <stdint.h>

#define BB   32
#define SS   512
#define CC   16
#define DIN  256
#define DOUT 64

#define XPAD 264   // bf16 row stride for Xs[b][k]
#define OPAD 72    // bf16 row stride for W chunk [k][o]
#define KC   64    // K per pipeline chunk
#define NCK  4     // number of chunks (256/64)

// Scratch (allocation-free rule: __device__ globals)
__device__ float g_uhat[(size_t)BB * CC * SS * DOUT]; // 64 MiB, [b][c][s][o]
__device__ float g_b[(size_t)BB * SS * CC];           // b_ij [b][s][c]
__device__ float g_c[(size_t)BB * SS * CC];           // c_ij [b][s][c]
__device__ float g_v[(size_t)BB * CC * DOUT];         // v_j  [b][c][o]

__device__ __forceinline__ uint32_t pack_bf2(float a, float b) {
    __nv_bfloat162 t = __floats2bfloat162_rn(a, b);
    return *reinterpret_cast<uint32_t*>(&t);
}

#define MMA_BF16(d, a, b)                                                     \
    asm volatile(                                                             \
        "mma.sync.aligned.m16n8k16.row.col.f32.bf16.bf16.f32 "                \
        "{%0,%1,%2,%3},{%4,%5,%6,%7},{%8,%9},{%0,%1,%2,%3};"                  \
        : "+f"(d[0]), "+f"(d[1]), "+f"(d[2]), "+f"(d[3])                      \
        : "r"(a[0]), "r"(a[1]), "r"(a[2]), "r"(a[3]), "r"(b[0]), "r"(b[1]))

// ---------------------------------------------------------------------------
// GEMM: u_hat[b,c,s,o] = sum_i x[b,s,i] * W[c,s,i,o]
// grid (S, C), 128 threads. Split-bf16 3-term MMA; W streamed in 4 chunks
// of K=64 with a double-buffered regs->smem pipeline.
// ---------------------------------------------------------------------------
__global__ void __launch_bounds__(128) gemm_uhat_kernel(const float* __restrict__ x,
                                                        const float* __restrict__ W) {
    extern __shared__ char raw[];
    __nv_bfloat16* Xh = (__nv_bfloat16*)raw;            // [32][XPAD]
    __nv_bfloat16* Xl = Xh + 32 * XPAD;
    __nv_bfloat16* Wh0 = Xl + 32 * XPAD;                // buf0 hi [KC][OPAD]
    __nv_bfloat16* Wl0 = Wh0 + KC * OPAD;               // buf0 lo
    __nv_bfloat16* Wh1 = Wl0 + KC * OPAD;               // buf1 hi
    __nv_bfloat16* Wl1 = Wh1 + KC * OPAD;               // buf1 lo

    __nv_bfloat16* WhB[2] = {Wh0, Wh1};
    __nv_bfloat16* WlB[2] = {Wl0, Wl1};

    const int s   = blockIdx.x;
    const int c   = blockIdx.y;
    const int tid = threadIdx.x;

    const float4* Wp4 = (const float4*)(W + ((size_t)c * SS + s) * (size_t)(DIN * DOUT));

    // prefetch W chunk 0 into regs (overlaps with X staging below)
    float4 wr[8];
#pragma unroll
    for (int j = 0; j < 8; j++) wr[j] = Wp4[j * 128 + tid];

    // ---- stage X tile (32 x 256 fp32) as hi/lo bf16 ----
    for (int i = tid; i < 2048; i += 128) {
        const int b = i >> 6;
        const int k = (i & 63) * 4;
        float4 f = ((const float4*)(x + ((size_t)b * SS + s) * DIN))[i & 63];
        float hx = __bfloat162float(__float2bfloat16(f.x));
        float hy = __bfloat162float(__float2bfloat16(f.y));
        float hz = __bfloat162float(__float2bfloat16(f.z));
        float hw = __bfloat162float(__float2bfloat16(f.w));
        *(uint32_t*)(Xh + b * XPAD + k)     = pack_bf2(f.x, f.y);
        *(uint32_t*)(Xh + b * XPAD + k + 2) = pack_bf2(f.z, f.w);
        *(uint32_t*)(Xl + b * XPAD + k)     = pack_bf2(f.x - hx, f.y - hy);
        *(uint32_t*)(Xl + b * XPAD + k + 2) = pack_bf2(f.z - hz, f.w - hw);
    }

    // convert chunk 0 -> buf0
#pragma unroll
    for (int j = 0; j < 8; j++) {
        const int i = j * 128 + tid;
        const int kr = i >> 4;
        const int o  = (i & 15) * 4;
        float4 f = wr[j];
        float hx = __bfloat162float(__float2bfloat16(f.x));
        float hy = __bfloat162float(__float2bfloat16(f.y));
        float hz = __bfloat162float(__float2bfloat16(f.z));
        float hw = __bfloat162float(__float2bfloat16(f.w));
        *(uint32_t*)(Wh0 + kr * OPAD + o)     = pack_bf2(f.x, f.y);
        *(uint32_t*)(Wh0 + kr * OPAD + o + 2) = pack_bf2(f.z, f.w);
        *(uint32_t*)(Wl0 + kr * OPAD + o)     = pack_bf2(f.x - hx, f.y - hy);
        *(uint32_t*)(Wl0 + kr * OPAD + o + 2) = pack_bf2(f.z - hz, f.w - hw);
    }
    __syncthreads();

    const int lane = tid & 31;
    const int warp = tid >> 5;
    const int nb   = warp * 16;          // warp's N range [nb, nb+16)
    const int ar   = lane >> 2;          // 0..7
    const int kq   = (lane & 3) * 2;     // 0,2,4,6

    float acc[2][2][4];
#pragma unroll
    for (int mt = 0; mt < 2; mt++)
#pragma unroll
        for (int nt = 0; nt < 2; nt++)
#pragma unroll
            for (int r = 0; r < 4; r++) acc[mt][nt][r] = 0.f;

#pragma unroll
    for (int ck = 0; ck < NCK; ck++) {
        // prefetch next W chunk
        if (ck < NCK - 1) {
#pragma unroll
            for (int j = 0; j < 8; j++) wr[j] = Wp4[(ck + 1) * 1024 + j * 128 + tid];
        }

        const unsigned short* WhU = (const unsigned short*)WhB[ck & 1];
        const unsigned short* WlU = (const unsigned short*)WlB[ck & 1];

#pragma unroll
        for (int kk = 0; kk < 4; kk++) {
            const int k0 = ck * KC + kk * 16;   // global k for X
            const int kl = kk * 16;             // chunk-local k for W

            uint32_t ah[2][4], al[2][4];
#pragma unroll
            for (int mt = 0; mt < 2; mt++) {
                const __nv_bfloat16* p = Xh + (ar + mt * 16) * XPAD + k0 + kq;
                const __nv_bfloat16* q = Xl + (ar + mt * 16) * XPAD + k0 + kq;
                ah[mt][0] = *(const uint32_t*)p;
                ah[mt][1] = *(const uint32_t*)(p + 8 * XPAD);
                ah[mt][2] = *(const uint32_t*)(p + 8);
                ah[mt][3] = *(const uint32_t*)(p + 8 * XPAD + 8);
                al[mt][0] = *(const uint32_t*)q;
                al[mt][1] = *(const uint32_t*)(q + 8 * XPAD);
                al[mt][2] = *(const uint32_t*)(q + 8);
                al[mt][3] = *(const uint32_t*)(q + 8 * XPAD + 8);
            }

            uint32_t bh[2][2], bl[2][2];
#pragma unroll
            for (int nt = 0; nt < 2; nt++) {
                const int n = nb + nt * 8 + ar;
                const int base = (kl + kq) * OPAD + n;
                bh[nt][0] = (uint32_t)WhU[base]            | ((uint32_t)WhU[base + OPAD]     << 16);
                bh[nt][1] = (uint32_t)WhU[base + 8 * OPAD] | ((uint32_t)WhU[base + 9 * OPAD] << 16);
                bl[nt][0] = (uint32_t)WlU[base]            | ((uint32_t)WlU[base + OPAD]     << 16);
                bl[nt][1] = (uint32_t)WlU[base + 8 * OPAD] | ((uint32_t)WlU[base + 9 * OPAD] << 16);
            }

#pragma unroll
            for (int mt = 0; mt < 2; mt++)
#pragma unroll
                for (int nt = 0; nt < 2; nt++) {
                    MMA_BF16(acc[mt][nt], ah[mt], bh[nt]);
                    MMA_BF16(acc[mt][nt], ah[mt], bl[nt]);
                    MMA_BF16(acc[mt][nt], al[mt], bh[nt]);
                }
        }

        // convert prefetched chunk into the other buffer
        if (ck < NCK - 1) {
            __nv_bfloat16* Whn = WhB[(ck + 1) & 1];
            __nv_bfloat16* Wln = WlB[(ck + 1) & 1];
#pragma unroll
            for (int j = 0; j < 8; j++) {
                const int i = j * 128 + tid;
                const int kr = i >> 4;
                const int o  = (i & 15) * 4;
                float4 f = wr[j];
                float hx = __bfloat162float(__float2bfloat16(f.x));
                float hy = __bfloat162float(__float2bfloat16(f.y));
                float hz = __bfloat162float(__float2bfloat16(f.z));
                float hw = __bfloat162float(__float2bfloat16(f.w));
                *(uint32_t*)(Whn + kr * OPAD + o)     = pack_bf2(f.x, f.y);
                *(uint32_t*)(Whn + kr * OPAD + o + 2) = pack_bf2(f.z, f.w);
                *(uint32_t*)(Wln + kr * OPAD + o)     = pack_bf2(f.x - hx, f.y - hy);
                *(uint32_t*)(Wln + kr * OPAD + o + 2) = pack_bf2(f.z - hz, f.w - hw);
            }
            __syncthreads();
        }
    }

    // ---- store: u_hat[b][c][s][o] ----
#pragma unroll
    for (int mt = 0; mt < 2; mt++) {
        const int row = ar + mt * 16;
#pragma unroll
        for (int nt = 0; nt < 2; nt++) {
            const int o = nb + nt * 8 + kq;
            float* p0 = g_uhat + (((size_t)row * CC + c) * SS + s) * DOUT + o;
            float* p1 = g_uhat + (((size_t)(row + 8) * CC + c) * SS + s) * DOUT + o;
            *(float2*)p0 = make_float2(acc[mt][nt][0], acc[mt][nt][1]);
            *(float2*)p1 = make_float2(acc[mt][nt][2], acc[mt][nt][3]);
        }
    }
}

// ---------------------------------------------------------------------------
// R1: s_j = sum_s c_ij * u_hat (per (b,c)); squash -> v. Streaming, no tile.
// mode 0: uniform (1/16); mode 1: weighted; mode 2: weighted + write d_out.
// ---------------------------------------------------------------------------
__global__ void __launch_bounds__(256) r1_sj_kernel(float* __restrict__ d_out, int mode) {
    __shared__ float cs[SS];
    __shared__ float red[256];
    __shared__ float sj[64];
    __shared__ float scl;

    const int bc  = blockIdx.x;
    const int b   = bc >> 4;
    const int c   = bc & 15;
    const int tid = threadIdx.x;

    if (mode != 0)
        for (int s = tid; s < SS; s += 256) cs[s] = g_c[((size_t)b * SS + s) * CC + c];
    __syncthreads();

    const int o  = tid & 63;
    const int sg = tid >> 6;
    const float* __restrict__ up = g_uhat + (size_t)bc * SS * DOUT;

    float acc = 0.f;
    if (mode == 0) {
#pragma unroll 8
        for (int s = sg; s < SS; s += 4) acc += up[s * DOUT + o];
        acc *= (1.0f / 16.0f);
    } else {
#pragma unroll 8
        for (int s = sg; s < SS; s += 4) acc += cs[s] * up[s * DOUT + o];
    }
    red[tid] = acc;
    __syncthreads();
    if (tid < 64) sj[tid] = red[tid] + red[tid + 64] + red[tid + 128] + red[tid + 192];
    __syncthreads();

    if (tid < 32) {
        float t = sj[tid] * sj[tid] + sj[tid + 32] * sj[tid + 32];
#pragma unroll
        for (int off = 16; off; off >>= 1) t += __shfl_xor_sync(0xffffffffu, t, off);
        if (tid == 0) {
            float n = sqrtf(t);
            scl = n / (1.0f + t);
        }
    }
    __syncthreads();
    if (tid < 64) {
        float v = sj[tid] * scl;
        g_v[(size_t)bc * DOUT + tid] = v;
        if (mode == 2) d_out[(size_t)bc * DOUT + tid] = v;
    }
}

// ---------------------------------------------------------------------------
// R2: agreement + softmax fused. Warp per (b,s): dot(u_hat[b,c,s,:], v[b,c,:])
// for all c, b_ij update, softmax over c -> c_ij. Block = 8 warps, same b.
// ---------------------------------------------------------------------------
__global__ void __launch_bounds__(256) r2_agree_softmax_kernel(int accumulate) {
    __shared__ float vs[CC * DOUT];   // v[b] : 16 x 64

    const int b     = blockIdx.x >> 6;            // 32 b's
    const int sbase = (blockIdx.x & 63) * 8;      // 64 s-groups of 8
    const int tid   = threadIdx.x;

    for (int i = tid; i < CC * DOUT; i += 256) vs[i] = g_v[(size_t)b * CC * DOUT + i];
    __syncthreads();

    const int warp = tid >> 5;
    const int lane = tid & 31;
    const int s    = sbase + warp;

    float myb = 0.f;
#pragma unroll
    for (int c = 0; c < CC; c++) {
        const float* __restrict__ u =
            g_uhat + (((size_t)b * CC + c) * SS + s) * DOUT;
        float d = u[lane] * vs[c * DOUT + lane] + u[lane + 32] * vs[c * DOUT + lane + 32];
#pragma unroll
        for (int off = 16; off; off >>= 1) d += __shfl_xor_sync(0xffffffffu, d, off);
        if (lane == c) myb = d;
    }

    float* bp = g_b + ((size_t)b * SS + s) * CC;
    if (lane < CC) {
        if (accumulate) myb += bp[lane];
        bp[lane] = myb;
    }

    // softmax over lanes 0..15
    float val = (lane < CC) ? myb : -INFINITY;
    float m = val;
#pragma unroll
    for (int off = 16; off; off >>= 1) m = fmaxf(m, __shfl_xor_sync(0xffffffffu, m, off));
    float e = __expf(val - m);
    float sum = e;
#pragma unroll
    for (int off = 16; off; off >>= 1) sum += __shfl_xor_sync(0xffffffffu, sum, off);
    if (lane < CC)
        g_c[((size_t)b * SS + s) * CC + lane] = e / sum;
}

// ---------------------------------------------------------------------------
extern "C" void kernel_launch(void* const* d_in, const int* in_sizes, int n_in,
                              void* d_out, int out_size) {
    const float* x = (const float*)d_in[0];   // [B,S,din]
    const float* W = (const float*)d_in[1];   // [C,S,din,dout]
    float* out = (float*)d_out;               // [B,C,dout]

    const int gsm = (2 * 32 * XPAD + 4 * KC * OPAD) * (int)sizeof(__nv_bfloat16); // 70656
    cudaFuncSetAttribute(gemm_uhat_kernel,
                         cudaFuncAttributeMaxDynamicSharedMemorySize, gsm);

    dim3 ggrid(SS, CC);
    gemm_uhat_kernel<<<ggrid, 128, gsm>>>(x, W);

    r1_sj_kernel<<<BB * CC, 256>>>(out, 0);          // it0: uniform c
    r2_agree_softmax_kernel<<<BB * 64, 256>>>(0);    // b = dot; c = softmax(b)
    r1_sj_kernel<<<BB * CC, 256>>>(out, 1);          // it1
    r2_agree_softmax_kernel<<<BB * 64, 256>>>(1);    // b += dot; c = softmax(b)
    r1_sj_kernel<<<BB * CC, 256>>>(out, 2);          // it2: final v -> out
}

// round 6
// speedup vs baseline: 2.9823x; 1.3651x over previous
#include <cuda_runtime.h>
#include <cuda_bf16.h>
#include <math.h>
#include <stdint.h>

#define BB   32
#define SS   512
#define CC   16
#define DIN  256
#define DOUT 64

#define XPAD 264       // bf16 row stride for Xs[b][k] (528B rows, ldmatrix conflict-free)
#define WSTRIDE 68     // fp32 row stride for W stage rows (bank = 4k+n, conflict-free)
#define KSTAGE 32      // K rows per cp.async stage
#define NSTAGES 4
#define NCHUNK 8       // 256 / 32

// Scratch (allocation-free rule: __device__ globals)
__device__ float g_uhat[(size_t)BB * CC * SS * DOUT]; // 64 MiB, [b][c][s][o]
__device__ float g_b[(size_t)BB * SS * CC];           // b_ij [b][s][c]
__device__ float g_c[(size_t)BB * SS * CC];           // c_ij [b][s][c]
__device__ float g_v[(size_t)BB * CC * DOUT];         // v_j  [b][c][o]

__device__ __forceinline__ uint32_t pack_bf2(float a, float b) {
    __nv_bfloat162 t = __floats2bfloat162_rn(a, b);
    return *reinterpret_cast<uint32_t*>(&t);
}

#define MMA_BF16(d, a, b)                                                     \
    asm volatile(                                                             \
        "mma.sync.aligned.m16n8k16.row.col.f32.bf16.bf16.f32 "                \
        "{%0,%1,%2,%3},{%4,%5,%6,%7},{%8,%9},{%0,%1,%2,%3};"                  \
        : "+f"(d[0]), "+f"(d[1]), "+f"(d[2]), "+f"(d[3])                      \
        : "r"(a[0]), "r"(a[1]), "r"(a[2]), "r"(a[3]), "r"(b[0]), "r"(b[1]))

#define LDSM_X4(r0, r1, r2, r3, addr)                                         \
    asm volatile("ldmatrix.sync.aligned.m8n8.x4.shared.b16 {%0,%1,%2,%3}, [%4];" \
                 : "=r"(r0), "=r"(r1), "=r"(r2), "=r"(r3) : "r"(addr))

// ---------------------------------------------------------------------------
// GEMM: u_hat[b,c,s,o] = sum_i x[b,s,i] * W[c,s,i,o]
// grid (S, C), 128 threads. W streamed raw fp32 via 4-stage cp.async ring;
// split-bf16 (truncation) conversion fused into B-fragment build; A via
// ldmatrix from pre-split hi/lo X tile.
// ---------------------------------------------------------------------------
__global__ void __launch_bounds__(128) gemm_uhat_kernel(const float* __restrict__ x,
                                                        const float* __restrict__ W) {
    extern __shared__ char raw[];
    __nv_bfloat16* Xh = (__nv_bfloat16*)raw;                 // [32][XPAD]
    __nv_bfloat16* Xl = Xh + 32 * XPAD;
    float* Wring = (float*)(Xl + 32 * XPAD);                 // [4][KSTAGE][WSTRIDE]

    const int s   = blockIdx.x;
    const int c   = blockIdx.y;
    const int tid = threadIdx.x;

    const float* Wp = W + ((size_t)c * SS + s) * (size_t)(DIN * DOUT);

    uint32_t wring_u32;
    {
        uint32_t tmp;
        asm("{ .reg .u64 t; cvta.to.shared.u64 t, %1; cvt.u32.u64 %0, t; }"
            : "=r"(tmp) : "l"((void*)Wring));
        wring_u32 = tmp;
    }

    // stage issue helper (4 cp.async of 16B per thread)
    const int wrow = tid >> 4;          // 0..7 (base row, step 8)
    const int wseg = tid & 15;          // 16B segment within 256B row
#define ISSUE_STAGE(slot, chunk)                                              \
    {                                                                         \
        const float* srcb = Wp + ((chunk) * KSTAGE) * DOUT + wseg * 4;        \
        uint32_t dstb = wring_u32 + (uint32_t)(slot) * (KSTAGE * WSTRIDE * 4) \
                        + wseg * 16;                                          \
        _Pragma("unroll")                                                     \
        for (int p = 0; p < 4; p++) {                                         \
            const int r = wrow + p * 8;                                       \
            asm volatile("cp.async.cg.shared.global [%0], [%1], 16;" ::       \
                         "r"(dstb + r * (WSTRIDE * 4)),                       \
                         "l"(srcb + r * DOUT) : "memory");                    \
        }                                                                     \
        asm volatile("cp.async.commit_group;" ::: "memory");                  \
    }

    // prologue: get W stream going immediately
    ISSUE_STAGE(0, 0);
    ISSUE_STAGE(1, 1);
    ISSUE_STAGE(2, 2);

    // ---- stage X tile (32 x 256 fp32) as hi/lo bf16 (RN split) ----
    for (int i = tid; i < 2048; i += 128) {
        const int b = i >> 6;
        const int k = (i & 63) * 4;
        float4 f = ((const float4*)(x + ((size_t)b * SS + s) * DIN))[i & 63];
        float hx = __bfloat162float(__float2bfloat16(f.x));
        float hy = __bfloat162float(__float2bfloat16(f.y));
        float hz = __bfloat162float(__float2bfloat16(f.z));
        float hw = __bfloat162float(__float2bfloat16(f.w));
        *(uint32_t*)(Xh + b * XPAD + k)     = pack_bf2(f.x, f.y);
        *(uint32_t*)(Xh + b * XPAD + k + 2) = pack_bf2(f.z, f.w);
        *(uint32_t*)(Xl + b * XPAD + k)     = pack_bf2(f.x - hx, f.y - hy);
        *(uint32_t*)(Xl + b * XPAD + k + 2) = pack_bf2(f.z - hz, f.w - hw);
    }

    const int lane = tid & 31;
    const int warp = tid >> 5;
    const int nb   = warp * 16;          // warp's N range [nb, nb+16)
    const int ar   = lane >> 2;          // 0..7
    const int kq   = (lane & 3) * 2;     // 0,2,4,6

    // ldmatrix lane addressing for A: row = lane&15 (+ mt*16), koff = (lane>>4)*8
    const int arow = lane & 15;
    const int akof = (lane >> 4) * 8;
    uint32_t xh_u32, xl_u32;
    {
        uint32_t t0, t1;
        asm("{ .reg .u64 t; cvta.to.shared.u64 t, %1; cvt.u32.u64 %0, t; }"
            : "=r"(t0) : "l"((void*)Xh));
        asm("{ .reg .u64 t; cvta.to.shared.u64 t, %1; cvt.u32.u64 %0, t; }"
            : "=r"(t1) : "l"((void*)Xl));
        xh_u32 = t0; xl_u32 = t1;
    }
    const uint32_t aoff0 = (uint32_t)((arow * XPAD + akof) * 2);
    const uint32_t aoff1 = (uint32_t)(((arow + 16) * XPAD + akof) * 2);

    float acc[2][2][4];
#pragma unroll
    for (int mt = 0; mt < 2; mt++)
#pragma unroll
        for (int nt = 0; nt < 2; nt++)
#pragma unroll
            for (int r = 0; r < 4; r++) acc[mt][nt][r] = 0.f;

#pragma unroll
    for (int ch = 0; ch < NCHUNK; ch++) {
        asm volatile("cp.async.wait_group 2;" ::: "memory");
        __syncthreads();
        // Commit a group EVERY iteration so wait_group 2 always implies
        // "chunk ch has landed" (empty commits on tail iterations).
        if (ch + 3 < NCHUNK) {
            ISSUE_STAGE((ch + 3) & 3, ch + 3);
        } else {
            asm volatile("cp.async.commit_group;" ::: "memory");
        }

        const float* Wst = Wring + (ch & 3) * (KSTAGE * WSTRIDE);

#pragma unroll
        for (int kk = 0; kk < 2; kk++) {
            const int k0 = ch * KSTAGE + kk * 16;   // global k for X
            const int kl = kk * 16;                 // stage-local k for W

            uint32_t ah[2][4], al[2][4];
            LDSM_X4(ah[0][0], ah[0][1], ah[0][2], ah[0][3], xh_u32 + aoff0 + k0 * 2);
            LDSM_X4(ah[1][0], ah[1][1], ah[1][2], ah[1][3], xh_u32 + aoff1 + k0 * 2);
            LDSM_X4(al[0][0], al[0][1], al[0][2], al[0][3], xl_u32 + aoff0 + k0 * 2);
            LDSM_X4(al[1][0], al[1][1], al[1][2], al[1][3], xl_u32 + aoff1 + k0 * 2);

            uint32_t bh[2][2], bl[2][2];
#pragma unroll
            for (int nt = 0; nt < 2; nt++) {
                const int n = nb + nt * 8 + ar;
#pragma unroll
                for (int kg = 0; kg < 2; kg++) {
                    const int krow = kl + kq + kg * 8;
                    float w0 = Wst[krow * WSTRIDE + n];
                    float w1 = Wst[(krow + 1) * WSTRIDE + n];
                    uint32_t u0 = __float_as_uint(w0);
                    uint32_t u1 = __float_as_uint(w1);
                    uint32_t hp;
                    asm("prmt.b32 %0, %1, %2, 0x7632;" : "=r"(hp) : "r"(u0), "r"(u1));
                    float l0 = w0 - __uint_as_float(u0 & 0xffff0000u);
                    float l1 = w1 - __uint_as_float(u1 & 0xffff0000u);
                    bh[nt][kg] = hp;
                    bl[nt][kg] = pack_bf2(l0, l1);
                }
            }

#pragma unroll
            for (int mt = 0; mt < 2; mt++)
#pragma unroll
                for (int nt = 0; nt < 2; nt++) {
                    MMA_BF16(acc[mt][nt], ah[mt], bh[nt]);
                    MMA_BF16(acc[mt][nt], ah[mt], bl[nt]);
                    MMA_BF16(acc[mt][nt], al[mt], bh[nt]);
                }
        }
    }

    // ---- store: u_hat[b][c][s][o] ----
#pragma unroll
    for (int mt = 0; mt < 2; mt++) {
        const int row = ar + mt * 16;
#pragma unroll
        for (int nt = 0; nt < 2; nt++) {
            const int o = nb + nt * 8 + kq;
            float* p0 = g_uhat + (((size_t)row * CC + c) * SS + s) * DOUT + o;
            float* p1 = g_uhat + (((size_t)(row + 8) * CC + c) * SS + s) * DOUT + o;
            *(float2*)p0 = make_float2(acc[mt][nt][0], acc[mt][nt][1]);
            *(float2*)p1 = make_float2(acc[mt][nt][2], acc[mt][nt][3]);
        }
    }
}

// ---------------------------------------------------------------------------
// R1: s_j = sum_s c_ij * u_hat (per (b,c)); squash -> v. float4 streaming.
// mode 0: uniform (1/16); mode 1: weighted; mode 2: weighted + write d_out.
// ---------------------------------------------------------------------------
__global__ void __launch_bounds__(256) r1_sj_kernel(float* __restrict__ d_out, int mode) {
    __shared__ float cs[SS];
    __shared__ float4 red4[256];
    __shared__ float sj[64];
    __shared__ float scl;

    const int bc  = blockIdx.x;
    const int b   = bc >> 4;
    const int c   = bc & 15;
    const int tid = threadIdx.x;

    if (mode != 0)
        for (int s = tid; s < SS; s += 256) cs[s] = g_c[((size_t)b * SS + s) * CC + c];
    __syncthreads();

    const int col = tid & 15;          // float4 column (o = col*4..col*4+3)
    const int sg  = tid >> 4;          // 16 s-groups
    const float4* __restrict__ up4 = (const float4*)(g_uhat + (size_t)bc * SS * DOUT);

    float4 acc = make_float4(0.f, 0.f, 0.f, 0.f);
    if (mode == 0) {
#pragma unroll 8
        for (int s = sg; s < SS; s += 16) {
            float4 u = up4[s * 16 + col];
            acc.x += u.x; acc.y += u.y; acc.z += u.z; acc.w += u.w;
        }
        acc.x *= (1.f/16.f); acc.y *= (1.f/16.f); acc.z *= (1.f/16.f); acc.w *= (1.f/16.f);
    } else {
#pragma unroll 8
        for (int s = sg; s < SS; s += 16) {
            float w = cs[s];
            float4 u = up4[s * 16 + col];
            acc.x += w * u.x; acc.y += w * u.y; acc.z += w * u.z; acc.w += w * u.w;
        }
    }
    red4[tid] = acc;
    __syncthreads();

    if (tid < 64) {
        const int cl = tid >> 2;       // float4 column
        const int cp = tid & 3;        // component
        float t = 0.f;
#pragma unroll
        for (int g = 0; g < 16; g++) {
            float4 v = red4[g * 16 + cl];
            t += (cp == 0) ? v.x : (cp == 1) ? v.y : (cp == 2) ? v.z : v.w;
        }
        sj[tid] = t;
    }
    __syncthreads();

    if (tid < 32) {
        float t = sj[tid] * sj[tid] + sj[tid + 32] * sj[tid + 32];
#pragma unroll
        for (int off = 16; off; off >>= 1) t += __shfl_xor_sync(0xffffffffu, t, off);
        if (tid == 0) {
            float n = sqrtf(t);
            scl = n / (1.0f + t);
        }
    }
    __syncthreads();
    if (tid < 64) {
        float v = sj[tid] * scl;
        g_v[(size_t)bc * DOUT + tid] = v;
        if (mode == 2) d_out[(size_t)bc * DOUT + tid] = v;
    }
}

// ---------------------------------------------------------------------------
// R2: agreement + softmax fused. Warp per (b,s).
// ---------------------------------------------------------------------------
__global__ void __launch_bounds__(256) r2_agree_softmax_kernel(int accumulate) {
    __shared__ float vs[CC * DOUT];   // v[b] : 16 x 64

    const int b     = blockIdx.x >> 6;            // 32 b's
    const int sbase = (blockIdx.x & 63) * 8;      // 64 s-groups of 8
    const int tid   = threadIdx.x;

    for (int i = tid; i < CC * DOUT; i += 256) vs[i] = g_v[(size_t)b * CC * DOUT + i];
    __syncthreads();

    const int warp = tid >> 5;
    const int lane = tid & 31;
    const int s    = sbase + warp;

    float myb = 0.f;
#pragma unroll
    for (int c = 0; c < CC; c++) {
        const float* __restrict__ u =
            g_uhat + (((size_t)b * CC + c) * SS + s) * DOUT;
        float d = u[lane] * vs[c * DOUT + lane] + u[lane + 32] * vs[c * DOUT + lane + 32];
#pragma unroll
        for (int off = 16; off; off >>= 1) d += __shfl_xor_sync(0xffffffffu, d, off);
        if (lane == c) myb = d;
    }

    float* bp = g_b + ((size_t)b * SS + s) * CC;
    if (lane < CC) {
        if (accumulate) myb += bp[lane];
        bp[lane] = myb;
    }

    float val = (lane < CC) ? myb : -INFINITY;
    float m = val;
#pragma unroll
    for (int off = 16; off; off >>= 1) m = fmaxf(m, __shfl_xor_sync(0xffffffffu, m, off));
    float e = __expf(val - m);
    float sum = e;
#pragma unroll
    for (int off = 16; off; off >>= 1) sum += __shfl_xor_sync(0xffffffffu, sum, off);
    if (lane < CC)
        g_c[((size_t)b * SS + s) * CC + lane] = e / sum;
}

// ---------------------------------------------------------------------------
extern "C" void kernel_launch(void* const* d_in, const int* in_sizes, int n_in,
                              void* d_out, int out_size) {
    const float* x = (const float*)d_in[0];   // [B,S,din]
    const float* W = (const float*)d_in[1];   // [C,S,din,dout]
    float* out = (float*)d_out;               // [B,C,dout]

    const int gsm = 2 * 32 * XPAD * (int)sizeof(__nv_bfloat16)
                  + NSTAGES * KSTAGE * WSTRIDE * (int)sizeof(float); // 33792+34816=68608
    cudaFuncSetAttribute(gemm_uhat_kernel,
                         cudaFuncAttributeMaxDynamicSharedMemorySize, gsm);

    dim3 ggrid(SS, CC);
    gemm_uhat_kernel<<<ggrid, 128, gsm>>>(x, W);

    r1_sj_kernel<<<BB * CC, 256>>>(out, 0);          // it0: uniform c
    r2_agree_softmax_kernel<<<BB * 64, 256>>>(0);    // b = dot; c = softmax(b)
    r1_sj_kernel<<<BB * CC, 256>>>(out, 1);          // it1
    r2_agree_softmax_kernel<<<BB * 64, 256>>>(1);    // b += dot; c = softmax(b)
    r1_sj_kernel<<<BB * CC, 256>>>(out, 2);          // it2: final v -> out
}

// round 7
// speedup vs baseline: 2.9917x; 1.0032x over previous
#include <cuda_runtime.h>
#include <cuda_bf16.h>
#include <math.h>
#include <stdint.h>

#define BB   32
#define SS   512
#define CC   16
#define DIN  256
#define DOUT 64

#define XPAD 264       // bf16 row stride for Xs[b][k] (528B rows, ldmatrix conflict-free)
#define WSTRIDE 68     // fp32 row stride for W stage rows (bank = 8q+ar, conflict-free)
#define KSTAGE 32      // K rows per cp.async stage
#define NSTAGES 4
#define NCHUNK 8       // 256 / 32

// Scratch (allocation-free rule: __device__ globals)
__device__ float g_uhat[(size_t)BB * CC * SS * DOUT]; // 64 MiB, [b][c][s][o]
__device__ float g_b[(size_t)BB * SS * CC];           // b_ij [b][s][c]
__device__ float g_v[(size_t)BB * CC * DOUT];         // v_j  [b][c][o]
__device__ float g_sjp[(size_t)8 * BB * CC * DOUT];   // s_j partial slices [w8][b][c][o]

__device__ __forceinline__ uint32_t pack_bf2(float a, float b) {
    __nv_bfloat162 t = __floats2bfloat162_rn(a, b);
    return *reinterpret_cast<uint32_t*>(&t);
}

#define MMA_BF16(d, a, b)                                                     \
    asm volatile(                                                             \
        "mma.sync.aligned.m16n8k16.row.col.f32.bf16.bf16.f32 "                \
        "{%0,%1,%2,%3},{%4,%5,%6,%7},{%8,%9},{%0,%1,%2,%3};"                  \
        : "+f"(d[0]), "+f"(d[1]), "+f"(d[2]), "+f"(d[3])                      \
        : "r"(a[0]), "r"(a[1]), "r"(a[2]), "r"(a[3]), "r"(b[0]), "r"(b[1]))

#define LDSM_X4(r0, r1, r2, r3, addr)                                         \
    asm volatile("ldmatrix.sync.aligned.m8n8.x4.shared.b16 {%0,%1,%2,%3}, [%4];" \
                 : "=r"(r0), "=r"(r1), "=r"(r2), "=r"(r3) : "r"(addr))

// ---------------------------------------------------------------------------
// GEMM: u_hat[b,c,s,o] = sum_i x[b,s,i] * W[c,s,i,o]
// grid (S, C), 128 threads. W streamed raw fp32 via 4-stage cp.async ring
// (3-chunk lookahead); split-bf16 (truncation) conversion fused into
// B-fragment build; A via ldmatrix from pre-split hi/lo X tile.
// ---------------------------------------------------------------------------
__global__ void __launch_bounds__(128) gemm_uhat_kernel(const float* __restrict__ x,
                                                        const float* __restrict__ W) {
    extern __shared__ char raw[];
    __nv_bfloat16* Xh = (__nv_bfloat16*)raw;                 // [32][XPAD]
    __nv_bfloat16* Xl = Xh + 32 * XPAD;
    float* Wring = (float*)(Xl + 32 * XPAD);                 // [4][KSTAGE][WSTRIDE]

    const int s   = blockIdx.x;
    const int c   = blockIdx.y;
    const int tid = threadIdx.x;

    const float* Wp = W + ((size_t)c * SS + s) * (size_t)(DIN * DOUT);

    uint32_t wring_u32;
    {
        uint32_t tmp;
        asm("{ .reg .u64 t; cvta.to.shared.u64 t, %1; cvt.u32.u64 %0, t; }"
            : "=r"(tmp) : "l"((void*)Wring));
        wring_u32 = tmp;
    }

    // stage issue helper (4 cp.async of 16B per thread)
    const int wrow = tid >> 4;          // 0..7 (base row, step 8)
    const int wseg = tid & 15;          // 16B segment within 256B row
#define ISSUE_STAGE(slot, chunk)                                              \
    {                                                                         \
        const float* srcb = Wp + ((chunk) * KSTAGE) * DOUT + wseg * 4;        \
        uint32_t dstb = wring_u32 + (uint32_t)(slot) * (KSTAGE * WSTRIDE * 4) \
                        + wseg * 16;                                          \
        _Pragma("unroll")                                                     \
        for (int p = 0; p < 4; p++) {                                         \
            const int r = wrow + p * 8;                                       \
            asm volatile("cp.async.cg.shared.global [%0], [%1], 16;" ::       \
                         "r"(dstb + r * (WSTRIDE * 4)),                       \
                         "l"(srcb + r * DOUT) : "memory");                    \
        }                                                                     \
        asm volatile("cp.async.commit_group;" ::: "memory");                  \
    }

    // prologue: get W stream going immediately (chunks 0,1,2)
    ISSUE_STAGE(0, 0);
    ISSUE_STAGE(1, 1);
    ISSUE_STAGE(2, 2);

    // ---- stage X tile (32 x 256 fp32) as hi/lo bf16 (RN split) ----
    for (int i = tid; i < 2048; i += 128) {
        const int b = i >> 6;
        const int k = (i & 63) * 4;
        float4 f = ((const float4*)(x + ((size_t)b * SS + s) * DIN))[i & 63];
        float hx = __bfloat162float(__float2bfloat16(f.x));
        float hy = __bfloat162float(__float2bfloat16(f.y));
        float hz = __bfloat162float(__float2bfloat16(f.z));
        float hw = __bfloat162float(__float2bfloat16(f.w));
        *(uint32_t*)(Xh + b * XPAD + k)     = pack_bf2(f.x, f.y);
        *(uint32_t*)(Xh + b * XPAD + k + 2) = pack_bf2(f.z, f.w);
        *(uint32_t*)(Xl + b * XPAD + k)     = pack_bf2(f.x - hx, f.y - hy);
        *(uint32_t*)(Xl + b * XPAD + k + 2) = pack_bf2(f.z - hz, f.w - hw);
    }

    const int lane = tid & 31;
    const int warp = tid >> 5;
    const int nb   = warp * 16;          // warp's N range [nb, nb+16)
    const int ar   = lane >> 2;          // 0..7
    const int kq   = (lane & 3) * 2;     // 0,2,4,6

    const int arow = lane & 15;
    const int akof = (lane >> 4) * 8;
    uint32_t xh_u32, xl_u32;
    {
        uint32_t t0, t1;
        asm("{ .reg .u64 t; cvta.to.shared.u64 t, %1; cvt.u32.u64 %0, t; }"
            : "=r"(t0) : "l"((void*)Xh));
        asm("{ .reg .u64 t; cvta.to.shared.u64 t, %1; cvt.u32.u64 %0, t; }"
            : "=r"(t1) : "l"((void*)Xl));
        xh_u32 = t0; xl_u32 = t1;
    }
    const uint32_t aoff0 = (uint32_t)((arow * XPAD + akof) * 2);
    const uint32_t aoff1 = (uint32_t)(((arow + 16) * XPAD + akof) * 2);

    float acc[2][2][4];
#pragma unroll
    for (int mt = 0; mt < 2; mt++)
#pragma unroll
        for (int nt = 0; nt < 2; nt++)
#pragma unroll
            for (int r = 0; r < 4; r++) acc[mt][nt][r] = 0.f;

#pragma unroll
    for (int ch = 0; ch < NCHUNK; ch++) {
        // 1) all warps done with chunk ch-1 (slot (ch+3)&3) and X staged
        __syncthreads();
        // 2) one group committed EVERY iteration: total groups = ch+4
        if (ch + 3 < NCHUNK) {
            ISSUE_STAGE((ch + 3) & 3, ch + 3);
        } else {
            asm volatile("cp.async.commit_group;" ::: "memory");
        }
        // 3) <=3 pending of ch+4 total => chunks 0..ch landed
        asm volatile("cp.async.wait_group 3;" ::: "memory");
        __syncthreads();

        const float* Wst = Wring + (ch & 3) * (KSTAGE * WSTRIDE);

#pragma unroll
        for (int kk = 0; kk < 2; kk++) {
            const int k0 = ch * KSTAGE + kk * 16;   // global k for X
            const int kl = kk * 16;                 // stage-local k for W

            uint32_t ah[2][4], al[2][4];
            LDSM_X4(ah[0][0], ah[0][1], ah[0][2], ah[0][3], xh_u32 + aoff0 + k0 * 2);
            LDSM_X4(ah[1][0], ah[1][1], ah[1][2], ah[1][3], xh_u32 + aoff1 + k0 * 2);
            LDSM_X4(al[0][0], al[0][1], al[0][2], al[0][3], xl_u32 + aoff0 + k0 * 2);
            LDSM_X4(al[1][0], al[1][1], al[1][2], al[1][3], xl_u32 + aoff1 + k0 * 2);

            uint32_t bh[2][2], bl[2][2];
#pragma unroll
            for (int nt = 0; nt < 2; nt++) {
                const int n = nb + nt * 8 + ar;
#pragma unroll
                for (int kg = 0; kg < 2; kg++) {
                    const int krow = kl + kq + kg * 8;
                    float w0 = Wst[krow * WSTRIDE + n];
                    float w1 = Wst[(krow + 1) * WSTRIDE + n];
                    uint32_t u0 = __float_as_uint(w0);
                    uint32_t u1 = __float_as_uint(w1);
                    uint32_t hp;
                    asm("prmt.b32 %0, %1, %2, 0x7632;" : "=r"(hp) : "r"(u0), "r"(u1));
                    float l0 = w0 - __uint_as_float(u0 & 0xffff0000u);
                    float l1 = w1 - __uint_as_float(u1 & 0xffff0000u);
                    bh[nt][kg] = hp;
                    bl[nt][kg] = pack_bf2(l0, l1);
                }
            }

#pragma unroll
            for (int mt = 0; mt < 2; mt++)
#pragma unroll
                for (int nt = 0; nt < 2; nt++) {
                    MMA_BF16(acc[mt][nt], ah[mt], bh[nt]);
                    MMA_BF16(acc[mt][nt], ah[mt], bl[nt]);
                    MMA_BF16(acc[mt][nt], al[mt], bh[nt]);
                }
        }
    }

    // ---- store: u_hat[b][c][s][o] ----
#pragma unroll
    for (int mt = 0; mt < 2; mt++) {
        const int row = ar + mt * 16;
#pragma unroll
        for (int nt = 0; nt < 2; nt++) {
            const int o = nb + nt * 8 + kq;
            float* p0 = g_uhat + (((size_t)row * CC + c) * SS + s) * DOUT + o;
            float* p1 = g_uhat + (((size_t)(row + 8) * CC + c) * SS + s) * DOUT + o;
            *(float2*)p0 = make_float2(acc[mt][nt][0], acc[mt][nt][1]);
            *(float2*)p1 = make_float2(acc[mt][nt][2], acc[mt][nt][3]);
        }
    }
}

// ---------------------------------------------------------------------------
// R1 (it0 only): s_j = (1/16) * sum_s u_hat -> squash -> v0.
// ---------------------------------------------------------------------------
__global__ void __launch_bounds__(256) r1_sj_kernel(void) {
    __shared__ float4 red4[256];
    __shared__ float sj[64];
    __shared__ float scl;

    const int bc  = blockIdx.x;
    const int tid = threadIdx.x;

    const int col = tid & 15;          // float4 column (o = col*4..col*4+3)
    const int sg  = tid >> 4;          // 16 s-groups
    const float4* __restrict__ up4 = (const float4*)(g_uhat + (size_t)bc * SS * DOUT);

    float4 acc = make_float4(0.f, 0.f, 0.f, 0.f);
#pragma unroll 8
    for (int s = sg; s < SS; s += 16) {
        float4 u = up4[s * 16 + col];
        acc.x += u.x; acc.y += u.y; acc.z += u.z; acc.w += u.w;
    }
    acc.x *= (1.f/16.f); acc.y *= (1.f/16.f); acc.z *= (1.f/16.f); acc.w *= (1.f/16.f);
    red4[tid] = acc;
    __syncthreads();

    if (tid < 64) {
        const int cl = tid >> 2;       // float4 column
        const int cp = tid & 3;        // component
        float t = 0.f;
#pragma unroll
        for (int g = 0; g < 16; g++) {
            float4 v = red4[g * 16 + cl];
            t += (cp == 0) ? v.x : (cp == 1) ? v.y : (cp == 2) ? v.z : v.w;
        }
        sj[tid] = t;
    }
    __syncthreads();

    if (tid < 32) {
        float t = sj[tid] * sj[tid] + sj[tid + 32] * sj[tid + 32];
#pragma unroll
        for (int off = 16; off; off >>= 1) t += __shfl_xor_sync(0xffffffffu, t, off);
        if (tid == 0) {
            float n = sqrtf(t);
            scl = n / (1.0f + t);
        }
    }
    __syncthreads();
    if (tid < 64)
        g_v[(size_t)bc * DOUT + tid] = sj[tid] * scl;
}

// ---------------------------------------------------------------------------
// F: fused agreement + b_ij update + softmax + weighted partial s_j.
// Warp owns 8 s values; u_hat held in registers, reused for dot and partial.
// Block = 8 warps (one 64-s window of one b); writes slice g_sjp[w8][b][:][:].
// ---------------------------------------------------------------------------
__global__ void __launch_bounds__(256) fused_route_kernel(int accumulate) {
    __shared__ float vs[CC * DOUT];          // v[b] : 16 x 64
    __shared__ float part[8 * CC * DOUT];    // per-warp partials, 32 KB

    const int b    = blockIdx.x >> 3;        // 32 b
    const int w8   = blockIdx.x & 7;         // 8 windows of 64 s
    const int tid  = threadIdx.x;
    const int warp = tid >> 5;
    const int lane = tid & 31;

    for (int i = tid; i < CC * DOUT; i += 256) vs[i] = g_v[(size_t)b * CC * DOUT + i];
    __syncthreads();

    float p0[CC], p1[CC];
#pragma unroll
    for (int c = 0; c < CC; c++) { p0[c] = 0.f; p1[c] = 0.f; }

    const int sbase = w8 * 64 + warp * 8;
    for (int si = 0; si < 8; si++) {
        const int s = sbase + si;

        float u0[CC], u1[CC];
#pragma unroll
        for (int c = 0; c < CC; c++) {
            const float* __restrict__ u =
                g_uhat + (((size_t)b * CC + c) * SS + s) * DOUT;
            u0[c] = u[lane];
            u1[c] = u[lane + 32];
        }

        // agreement dots (per c, warp-reduced); lane c holds dot for capsule c
        float myb = 0.f;
#pragma unroll
        for (int c = 0; c < CC; c++) {
            float d = u0[c] * vs[c * DOUT + lane] + u1[c] * vs[c * DOUT + lane + 32];
#pragma unroll
            for (int off = 16; off; off >>= 1) d += __shfl_xor_sync(0xffffffffu, d, off);
            if (lane == c) myb = d;
        }

        // b_ij update
        float* bp = g_b + ((size_t)b * SS + s) * CC;
        if (lane < CC) {
            if (accumulate) myb += bp[lane];
            bp[lane] = myb;
        }

        // softmax over lanes 0..15
        float val = (lane < CC) ? myb : -INFINITY;
        float m = val;
#pragma unroll
        for (int off = 16; off; off >>= 1) m = fmaxf(m, __shfl_xor_sync(0xffffffffu, m, off));
        float e = __expf(val - m);
        float sum = e;
#pragma unroll
        for (int off = 16; off; off >>= 1) sum += __shfl_xor_sync(0xffffffffu, sum, off);
        float cv = e / sum;  // valid in lanes < 16

        // weighted partial s_j accumulation (reuses u regs)
#pragma unroll
        for (int c = 0; c < CC; c++) {
            float w = __shfl_sync(0xffffffffu, cv, c);
            p0[c] += w * u0[c];
            p1[c] += w * u1[c];
        }
    }

    // per-warp partials -> smem
#pragma unroll
    for (int c = 0; c < CC; c++) {
        part[warp * (CC * DOUT) + c * DOUT + lane]      = p0[c];
        part[warp * (CC * DOUT) + c * DOUT + lane + 32] = p1[c];
    }
    __syncthreads();

    // reduce 8 warps -> deterministic slice write
#pragma unroll
    for (int j = 0; j < 4; j++) {
        const int co = tid + j * 256;   // 0..1023 over (c,o)
        float t = 0.f;
#pragma unroll
        for (int w = 0; w < 8; w++) t += part[w * (CC * DOUT) + co];
        g_sjp[(size_t)w8 * (BB * CC * DOUT) + (size_t)b * (CC * DOUT) + co] = t;
    }
}

// ---------------------------------------------------------------------------
// finish: sum 8 slices -> s_j; squash -> v (and optionally d_out).
// grid = B*C blocks of 64 threads.
// ---------------------------------------------------------------------------
__global__ void __launch_bounds__(64) finish_kernel(float* __restrict__ d_out, int write_out) {
    __shared__ float sh[64];
    __shared__ float scl;
    const int bc = blockIdx.x;
    const int o  = threadIdx.x;

    float sjv = 0.f;
#pragma unroll
    for (int w = 0; w < 8; w++)
        sjv += g_sjp[(size_t)w * (BB * CC * DOUT) + (size_t)bc * DOUT + o];

    sh[o] = sjv * sjv;
    __syncthreads();
    if (o < 32) {
        float t = sh[o] + sh[o + 32];
#pragma unroll
        for (int off = 16; off; off >>= 1) t += __shfl_xor_sync(0xffffffffu, t, off);
        if (o == 0) scl = sqrtf(t) / (1.0f + t);
    }
    __syncthreads();
    float v = sjv * scl;
    g_v[(size_t)bc * DOUT + o] = v;
    if (write_out) d_out[(size_t)bc * DOUT + o] = v;
}

// ---------------------------------------------------------------------------
extern "C" void kernel_launch(void* const* d_in, const int* in_sizes, int n_in,
                              void* d_out, int out_size) {
    const float* x = (const float*)d_in[0];   // [B,S,din]
    const float* W = (const float*)d_in[1];   // [C,S,din,dout]
    float* out = (float*)d_out;               // [B,C,dout]

    const int gsm = 2 * 32 * XPAD * (int)sizeof(__nv_bfloat16)
                  + NSTAGES * KSTAGE * WSTRIDE * (int)sizeof(float); // 68608
    cudaFuncSetAttribute(gemm_uhat_kernel,
                         cudaFuncAttributeMaxDynamicSharedMemorySize, gsm);

    dim3 ggrid(SS, CC);
    gemm_uhat_kernel<<<ggrid, 128, gsm>>>(x, W);

    r1_sj_kernel<<<BB * CC, 256>>>();                 // it0: uniform c -> v0
    fused_route_kernel<<<BB * 8, 256>>>(0);           // b=dot; softmax; partial s_j(it1)
    finish_kernel<<<BB * CC, 64>>>(out, 0);           // squash -> v1
    fused_route_kernel<<<BB * 8, 256>>>(1);           // b+=dot; softmax; partial s_j(it2)
    finish_kernel<<<BB * CC, 64>>>(out, 1);           // squash -> v2 -> d_out
}

// round 8
// speedup vs baseline: 3.0683x; 1.0256x over previous
#include <cuda_runtime.h>
#include <cuda_bf16.h>
#include <math.h>
#include <stdint.h>

#define BB   32
#define SS   512
#define CC   16
#define DIN  256
#define DOUT 64

#define XPAD 264       // bf16 row stride for Xs[b][k] (528B rows, ldmatrix conflict-free)
#define WSTRIDE 68     // fp32 row stride for W stage rows (bank = 8q+ar, conflict-free)
#define KSTAGE 32      // K rows per cp.async stage
#define NSTAGES 4
#define NCHUNK 8       // 256 / 32

// Scratch (allocation-free rule: __device__ globals)
__device__ float g_uhat[(size_t)BB * SS * CC * DOUT]; // 64 MiB, [b][s][c][o]  (TRANSPOSED)
__device__ float g_b[(size_t)BB * SS * CC];           // b_ij [b][s][c]
__device__ float g_v[(size_t)BB * CC * DOUT];         // v_j  [b][c][o] (it0 only)
__device__ float4 g_sjp[2][(size_t)8 * BB * 256];     // s_j slices [buf][w8][b][(c,o)/4]

__device__ __forceinline__ uint32_t pack_bf2(float a, float b) {
    __nv_bfloat162 t = __floats2bfloat162_rn(a, b);
    return *reinterpret_cast<uint32_t*>(&t);
}

#define MMA_BF16(d, a, b)                                                     \
    asm volatile(                                                             \
        "mma.sync.aligned.m16n8k16.row.col.f32.bf16.bf16.f32 "                \
        "{%0,%1,%2,%3},{%4,%5,%6,%7},{%8,%9},{%0,%1,%2,%3};"                  \
        : "+f"(d[0]), "+f"(d[1]), "+f"(d[2]), "+f"(d[3])                      \
        : "r"(a[0]), "r"(a[1]), "r"(a[2]), "r"(a[3]), "r"(b[0]), "r"(b[1]))

#define LDSM_X4(r0, r1, r2, r3, addr)                                         \
    asm volatile("ldmatrix.sync.aligned.m8n8.x4.shared.b16 {%0,%1,%2,%3}, [%4];" \
                 : "=r"(r0), "=r"(r1), "=r"(r2), "=r"(r3) : "r"(addr))

// ---------------------------------------------------------------------------
// GEMM: u_hat[b,s,c,o] = sum_i x[b,s,i] * W[c,s,i,o]
// grid (S, C), 128 threads. W streamed raw fp32 via 4-stage cp.async ring;
// split-bf16 (truncation) conversion fused into B-fragment build; A via
// ldmatrix from pre-split hi/lo X tile.
// ---------------------------------------------------------------------------
__global__ void __launch_bounds__(128) gemm_uhat_kernel(const float* __restrict__ x,
                                                        const float* __restrict__ W) {
    extern __shared__ char raw[];
    __nv_bfloat16* Xh = (__nv_bfloat16*)raw;                 // [32][XPAD]
    __nv_bfloat16* Xl = Xh + 32 * XPAD;
    float* Wring = (float*)(Xl + 32 * XPAD);                 // [4][KSTAGE][WSTRIDE]

    const int s   = blockIdx.x;
    const int c   = blockIdx.y;
    const int tid = threadIdx.x;

    const float* Wp = W + ((size_t)c * SS + s) * (size_t)(DIN * DOUT);

    uint32_t wring_u32;
    {
        uint32_t tmp;
        asm("{ .reg .u64 t; cvta.to.shared.u64 t, %1; cvt.u32.u64 %0, t; }"
            : "=r"(tmp) : "l"((void*)Wring));
        wring_u32 = tmp;
    }

    const int wrow = tid >> 4;          // 0..7 (base row, step 8)
    const int wseg = tid & 15;          // 16B segment within 256B row
#define ISSUE_STAGE(slot, chunk)                                              \
    {                                                                         \
        const float* srcb = Wp + ((chunk) * KSTAGE) * DOUT + wseg * 4;        \
        uint32_t dstb = wring_u32 + (uint32_t)(slot) * (KSTAGE * WSTRIDE * 4) \
                        + wseg * 16;                                          \
        _Pragma("unroll")                                                     \
        for (int p = 0; p < 4; p++) {                                         \
            const int r = wrow + p * 8;                                       \
            asm volatile("cp.async.cg.shared.global [%0], [%1], 16;" ::       \
                         "r"(dstb + r * (WSTRIDE * 4)),                       \
                         "l"(srcb + r * DOUT) : "memory");                    \
        }                                                                     \
        asm volatile("cp.async.commit_group;" ::: "memory");                  \
    }

    ISSUE_STAGE(0, 0);
    ISSUE_STAGE(1, 1);
    ISSUE_STAGE(2, 2);

    // ---- stage X tile (32 x 256 fp32) as hi/lo bf16 (RN split) ----
    for (int i = tid; i < 2048; i += 128) {
        const int b = i >> 6;
        const int k = (i & 63) * 4;
        float4 f = ((const float4*)(x + ((size_t)b * SS + s) * DIN))[i & 63];
        float hx = __bfloat162float(__float2bfloat16(f.x));
        float hy = __bfloat162float(__float2bfloat16(f.y));
        float hz = __bfloat162float(__float2bfloat16(f.z));
        float hw = __bfloat162float(__float2bfloat16(f.w));
        *(uint32_t*)(Xh + b * XPAD + k)     = pack_bf2(f.x, f.y);
        *(uint32_t*)(Xh + b * XPAD + k + 2) = pack_bf2(f.z, f.w);
        *(uint32_t*)(Xl + b * XPAD + k)     = pack_bf2(f.x - hx, f.y - hy);
        *(uint32_t*)(Xl + b * XPAD + k + 2) = pack_bf2(f.z - hz, f.w - hw);
    }

    const int lane = tid & 31;
    const int warp = tid >> 5;
    const int nb   = warp * 16;
    const int ar   = lane >> 2;          // 0..7
    const int kq   = (lane & 3) * 2;     // 0,2,4,6

    const int arow = lane & 15;
    const int akof = (lane >> 4) * 8;
    uint32_t xh_u32, xl_u32;
    {
        uint32_t t0, t1;
        asm("{ .reg .u64 t; cvta.to.shared.u64 t, %1; cvt.u32.u64 %0, t; }"
            : "=r"(t0) : "l"((void*)Xh));
        asm("{ .reg .u64 t; cvta.to.shared.u64 t, %1; cvt.u32.u64 %0, t; }"
            : "=r"(t1) : "l"((void*)Xl));
        xh_u32 = t0; xl_u32 = t1;
    }
    const uint32_t aoff0 = (uint32_t)((arow * XPAD + akof) * 2);
    const uint32_t aoff1 = (uint32_t)(((arow + 16) * XPAD + akof) * 2);

    float acc[2][2][4];
#pragma unroll
    for (int mt = 0; mt < 2; mt++)
#pragma unroll
        for (int nt = 0; nt < 2; nt++)
#pragma unroll
            for (int r = 0; r < 4; r++) acc[mt][nt][r] = 0.f;

#pragma unroll
    for (int ch = 0; ch < NCHUNK; ch++) {
        __syncthreads();
        if (ch + 3 < NCHUNK) {
            ISSUE_STAGE((ch + 3) & 3, ch + 3);
        } else {
            asm volatile("cp.async.commit_group;" ::: "memory");
        }
        asm volatile("cp.async.wait_group 3;" ::: "memory");
        __syncthreads();

        const float* Wst = Wring + (ch & 3) * (KSTAGE * WSTRIDE);

#pragma unroll
        for (int kk = 0; kk < 2; kk++) {
            const int k0 = ch * KSTAGE + kk * 16;
            const int kl = kk * 16;

            uint32_t ah[2][4], al[2][4];
            LDSM_X4(ah[0][0], ah[0][1], ah[0][2], ah[0][3], xh_u32 + aoff0 + k0 * 2);
            LDSM_X4(ah[1][0], ah[1][1], ah[1][2], ah[1][3], xh_u32 + aoff1 + k0 * 2);
            LDSM_X4(al[0][0], al[0][1], al[0][2], al[0][3], xl_u32 + aoff0 + k0 * 2);
            LDSM_X4(al[1][0], al[1][1], al[1][2], al[1][3], xl_u32 + aoff1 + k0 * 2);

            uint32_t bh[2][2], bl[2][2];
#pragma unroll
            for (int nt = 0; nt < 2; nt++) {
                const int n = nb + nt * 8 + ar;
#pragma unroll
                for (int kg = 0; kg < 2; kg++) {
                    const int krow = kl + kq + kg * 8;
                    float w0 = Wst[krow * WSTRIDE + n];
                    float w1 = Wst[(krow + 1) * WSTRIDE + n];
                    uint32_t u0 = __float_as_uint(w0);
                    uint32_t u1 = __float_as_uint(w1);
                    uint32_t hp;
                    asm("prmt.b32 %0, %1, %2, 0x7632;" : "=r"(hp) : "r"(u0), "r"(u1));
                    float l0 = w0 - __uint_as_float(u0 & 0xffff0000u);
                    float l1 = w1 - __uint_as_float(u1 & 0xffff0000u);
                    bh[nt][kg] = hp;
                    bl[nt][kg] = pack_bf2(l0, l1);
                }
            }

#pragma unroll
            for (int mt = 0; mt < 2; mt++)
#pragma unroll
                for (int nt = 0; nt < 2; nt++) {
                    MMA_BF16(acc[mt][nt], ah[mt], bh[nt]);
                    MMA_BF16(acc[mt][nt], ah[mt], bl[nt]);
                    MMA_BF16(acc[mt][nt], al[mt], bh[nt]);
                }
        }
    }

    // ---- store: u_hat[b][s][c][o] (transposed layout) ----
#pragma unroll
    for (int mt = 0; mt < 2; mt++) {
        const int row = ar + mt * 16;
#pragma unroll
        for (int nt = 0; nt < 2; nt++) {
            const int o = nb + nt * 8 + kq;
            float* p0 = g_uhat + (((size_t)row * SS + s) * CC + c) * DOUT + o;
            float* p1 = g_uhat + (((size_t)(row + 8) * SS + s) * CC + c) * DOUT + o;
            *(float2*)p0 = make_float2(acc[mt][nt][0], acc[mt][nt][1]);
            *(float2*)p1 = make_float2(acc[mt][nt][2], acc[mt][nt][3]);
        }
    }
}

// ---------------------------------------------------------------------------
// R1 (it0): s_j = (1/16) * sum_s u_hat[b,s,c,:] -> squash -> g_v.
// grid = B*C, 256 threads. [b][s][c][o] layout.
// ---------------------------------------------------------------------------
__global__ void __launch_bounds__(256) r1_sj_kernel(void) {
    __shared__ float4 red4[256];
    __shared__ float sj[64];
    __shared__ float scl;

    const int bc  = blockIdx.x;
    const int b   = bc >> 4;
    const int c   = bc & 15;
    const int tid = threadIdx.x;

    const int col = tid & 15;          // o-quad
    const int sg  = tid >> 4;          // 16 s-groups
    const float4* __restrict__ up4 = (const float4*)g_uhat;
    const size_t base = (size_t)b * SS * 256 + (size_t)c * 16;  // float4 units

    float4 acc = make_float4(0.f, 0.f, 0.f, 0.f);
#pragma unroll 8
    for (int s = sg; s < SS; s += 16) {
        float4 u = up4[base + (size_t)s * 256 + col];
        acc.x += u.x; acc.y += u.y; acc.z += u.z; acc.w += u.w;
    }
    acc.x *= (1.f/16.f); acc.y *= (1.f/16.f); acc.z *= (1.f/16.f); acc.w *= (1.f/16.f);
    red4[tid] = acc;
    __syncthreads();

    if (tid < 64) {
        const int cl = tid >> 2;
        const int cp = tid & 3;
        float t = 0.f;
#pragma unroll
        for (int g = 0; g < 16; g++) {
            float4 v = red4[g * 16 + cl];
            t += (cp == 0) ? v.x : (cp == 1) ? v.y : (cp == 2) ? v.z : v.w;
        }
        sj[tid] = t;
    }
    __syncthreads();

    if (tid < 32) {
        float t = sj[tid] * sj[tid] + sj[tid + 32] * sj[tid + 32];
#pragma unroll
        for (int off = 16; off; off >>= 1) t += __shfl_xor_sync(0xffffffffu, t, off);
        if (tid == 0) scl = sqrtf(t) / (1.0f + t);
    }
    __syncthreads();
    if (tid < 64)
        g_v[(size_t)bc * DOUT + tid] = sj[tid] * scl;
}

// ---------------------------------------------------------------------------
// F: fused (v-build) + agreement + b_ij + softmax + weighted partial s_j.
// Warp per s (8 s per warp). u_hat [b][s][c][o]: warp tile = 16x64 contiguous.
// Lane holds float4 j=0..7 at (c = 2j + lane/16, o = (lane%16)*4 ..+3).
// mode 0: v from g_v, b_ij = dot, write slices -> buf0
// mode 1: v from reduce(buf0)+squash, b_ij += dot, write slices -> buf1
// ---------------------------------------------------------------------------
__global__ void __launch_bounds__(256) fused_route_kernel(int mode) {
    __shared__ float4 vs4[256];       // v[b] as (c,o)/4
    __shared__ float4 part4[8 * 256]; // per-warp partial s_j
    __shared__ float  sdot[8 * 16];   // per-warp dots / c_ij

    const int b    = blockIdx.x >> 3;
    const int w8   = blockIdx.x & 7;
    const int tid  = threadIdx.x;
    const int warp = tid >> 5;
    const int lane = tid & 31;
    const int hf   = lane >> 4;       // half: capsule parity
    const int l16  = lane & 15;

    // ---- build v in smem ----
    if (mode == 0) {
        vs4[tid] = ((const float4*)(g_v + (size_t)b * CC * DOUT))[tid];
    } else {
        float4 a = make_float4(0.f, 0.f, 0.f, 0.f);
#pragma unroll
        for (int w = 0; w < 8; w++) {
            float4 t = g_sjp[0][(size_t)w * (BB * 256) + (size_t)b * 256 + tid];
            a.x += t.x; a.y += t.y; a.z += t.z; a.w += t.w;
        }
        float ss = a.x * a.x + a.y * a.y + a.z * a.z + a.w * a.w;
#pragma unroll
        for (int off = 8; off; off >>= 1) ss += __shfl_xor_sync(0xffffffffu, ss, off);
        float sc = sqrtf(ss) / (1.0f + ss);   // same value across the 16-lane c-group
        vs4[tid] = make_float4(a.x * sc, a.y * sc, a.z * sc, a.w * sc);
    }
    __syncthreads();

    float4 p[8];
#pragma unroll
    for (int j = 0; j < 8; j++) p[j] = make_float4(0.f, 0.f, 0.f, 0.f);

    const int sbase = w8 * 64 + warp * 8;
    for (int si = 0; si < 8; si++) {
        const int s = sbase + si;
        const float4* __restrict__ up = (const float4*)(g_uhat + ((size_t)b * SS + s) * 1024);

        float4 u[8];
#pragma unroll
        for (int j = 0; j < 8; j++) u[j] = up[j * 32 + lane];

        // dots: d_c = sum_o u*v for c = 2j+hf; 4-step half-warp reduce per j
#pragma unroll
        for (int j = 0; j < 8; j++) {
            float4 v = vs4[(2 * j + hf) * 16 + l16];
            float d = u[j].x * v.x + u[j].y * v.y + u[j].z * v.z + u[j].w * v.w;
#pragma unroll
            for (int off = 8; off; off >>= 1) d += __shfl_xor_sync(0xffffffffu, d, off);
            if (l16 == 0) sdot[warp * 16 + 2 * j + hf] = d;
        }
        __syncwarp();

        // b_ij update + softmax (lanes 0..15)
        if (lane < 16) {
            float t = sdot[warp * 16 + lane];
            float* bp = g_b + ((size_t)b * SS + s) * CC;
            if (mode == 1) t += bp[lane];
            bp[lane] = t;
            float m = t;
#pragma unroll
            for (int off = 8; off; off >>= 1)
                m = fmaxf(m, __shfl_xor_sync(0xffffu, m, off));
            float e = __expf(t - m);
            float sum = e;
#pragma unroll
            for (int off = 8; off; off >>= 1)
                sum += __shfl_xor_sync(0xffffu, sum, off);
            sdot[warp * 16 + lane] = e / sum;      // c_ij
        }
        __syncwarp();

        // weighted accumulation (reuses u regs)
#pragma unroll
        for (int j = 0; j < 8; j++) {
            float w = sdot[warp * 16 + 2 * j + hf];   // broadcast within half
            p[j].x += w * u[j].x; p[j].y += w * u[j].y;
            p[j].z += w * u[j].z; p[j].w += w * u[j].w;
        }
    }

    // per-warp partials -> smem, then block reduce (deterministic)
#pragma unroll
    for (int j = 0; j < 8; j++) part4[warp * 256 + j * 32 + lane] = p[j];
    __syncthreads();

    float4 t = make_float4(0.f, 0.f, 0.f, 0.f);
#pragma unroll
    for (int w = 0; w < 8; w++) {
        float4 q = part4[w * 256 + tid];
        t.x += q.x; t.y += q.y; t.z += q.z; t.w += q.w;
    }
    g_sjp[mode][(size_t)w8 * (BB * 256) + (size_t)b * 256 + tid] = t;
}

// ---------------------------------------------------------------------------
// finish: reduce buf1 slices -> s_j; squash -> d_out. grid B*C x 64.
// ---------------------------------------------------------------------------
__global__ void __launch_bounds__(64) finish_kernel(float* __restrict__ d_out) {
    __shared__ float sh[64];
    __shared__ float scl;
    const int bc = blockIdx.x;
    const int b  = bc >> 4;
    const int c  = bc & 15;
    const int o  = threadIdx.x;

    const float* base = (const float*)&g_sjp[1][0];
    float sjv = 0.f;
#pragma unroll
    for (int w = 0; w < 8; w++)
        sjv += base[((size_t)w * BB + b) * 1024 + c * 64 + o];

    sh[o] = sjv * sjv;
    __syncthreads();
    if (o < 32) {
        float t = sh[o] + sh[o + 32];
#pragma unroll
        for (int off = 16; off; off >>= 1) t += __shfl_xor_sync(0xffffffffu, t, off);
        if (o == 0) scl = sqrtf(t) / (1.0f + t);
    }
    __syncthreads();
    d_out[(size_t)bc * DOUT + o] = sjv * scl;
}

// ---------------------------------------------------------------------------
extern "C" void kernel_launch(void* const* d_in, const int* in_sizes, int n_in,
                              void* d_out, int out_size) {
    const float* x = (const float*)d_in[0];   // [B,S,din]
    const float* W = (const float*)d_in[1];   // [C,S,din,dout]
    float* out = (float*)d_out;               // [B,C,dout]

    const int gsm = 2 * 32 * XPAD * (int)sizeof(__nv_bfloat16)
                  + NSTAGES * KSTAGE * WSTRIDE * (int)sizeof(float); // 68608
    cudaFuncSetAttribute(gemm_uhat_kernel,
                         cudaFuncAttributeMaxDynamicSharedMemorySize, gsm);

    dim3 ggrid(SS, CC);
    gemm_uhat_kernel<<<ggrid, 128, gsm>>>(x, W);

    r1_sj_kernel<<<BB * CC, 256>>>();         // it0: uniform -> v0
    fused_route_kernel<<<BB * 8, 256>>>(0);   // dots(v0); b=dot; c=softmax; s_j -> buf0
    fused_route_kernel<<<BB * 8, 256>>>(1);   // v1=squash(buf0); b+=dot; s_j -> buf1
    finish_kernel<<<BB * CC, 64>>>(out);      // v2=squash(buf1) -> out
}